// round 3
// baseline (speedup 1.0000x reference)
#include <cuda_runtime.h>

#define BATCH 4096
#define NN 64
#define HH 16
#define FALLBACK_SIZE 12

__device__ float    g_partials[BATCH];
__device__ unsigned g_count = 0;

__device__ __forceinline__ float sigmoid3(float g) {
    float th;
    asm("tanh.approx.f32 %0, %1;" : "=f"(th) : "f"(1.5f * g));
    return fmaf(0.5f, th, 0.5f);
}

__global__ __launch_bounds__(256) void energy_kernel(
    const float* __restrict__ grid,   // [B,1,64,64]
    const float* __restrict__ hints,  // [B,2,64,16]
    const float* __restrict__ wg,     // [1,64,64]
    const float* __restrict__ wh,     // [2,64,16]
    float* __restrict__ out)
{
    __shared__ float s_s [NN][NN];    // sigmoid(3*grid)
    __shared__ float s_g2[NN][NN];    // grid^2
    __shared__ float s_row_target[NN];
    __shared__ float s_col_target[NN];
    __shared__ float s_cp[4][NN];     // column partials (4 row-quarters)
    __shared__ float s_warp[8];
    __shared__ int   s_last[2];
    __shared__ bool  s_is_last;
    __shared__ double s_dwarp[8];

    const int b = blockIdx.x;
    const int t = threadIdx.x;
    const int lane = t & 31;
    const int wid  = t >> 5;

    const float* gb = grid  + (size_t)b * (NN * NN);
    const float* hb = hints + (size_t)b * (2 * NN * HH);

    float neural = 0.f;

    // ================= Phase A: no barrier, no masks ====================
    // Hints -> targets (+ neural part).  t<128: one hint row each.
    if (t < 128) {
        const int k = t >> 6;      // 0 = row hints, 1 = col hints
        const int r = t & 63;
        const float4* hp = (const float4*)(hb + k * (NN * HH) + r * HH);
        const float4* wp = (const float4*)(wh + k * (NN * HH) + r * HH);
        float tsum = 0.f;
        #pragma unroll
        for (int q = 0; q < 4; q++) {
            float4 h = hp[q];
            float4 w = wp[q];
            tsum   += h.x + h.y + h.z + h.w;
            neural += h.x * w.x + h.y * w.y + h.z * w.z + h.w * w.w;
        }
        if (k == 0) s_row_target[r] = tsum;
        else        s_col_target[r] = tsum;
    }

    // Grid pass: thread t -> row i = t/4, 16 contiguous cols (cg = t%4).
    // Unmasked: neural dot, sigmoid -> s_s, g^2 -> s_g2.
    const int i  = t >> 2;
    const int cg = t & 3;
    {
        const float4* gp  = (const float4*)(gb + i * NN + cg * 16);
        const float4* wgp = (const float4*)(wg + i * NN + cg * 16);
        #pragma unroll
        for (int q = 0; q < 4; q++) {
            float4 g = gp[q];
            float4 w = wgp[q];
            neural += g.x * w.x + g.y * w.y + g.z * w.z + g.w * w.w;
            float4 sv, g2v;
            sv.x = sigmoid3(g.x);  g2v.x = g.x * g.x;
            sv.y = sigmoid3(g.y);  g2v.y = g.y * g.y;
            sv.z = sigmoid3(g.z);  g2v.z = g.z * g.z;
            sv.w = sigmoid3(g.w);  g2v.w = g.w * g.w;
            *(float4*)&s_s [i][cg * 16 + q * 4] = sv;
            *(float4*)&s_g2[i][cg * 16 + q * 4] = g2v;
        }
    }
    __syncthreads();

    // ================= Phase B: puzzle size ============================
    if (wid < 2) {
        const float* tgt = (wid == 0) ? s_row_target : s_col_target;
        int v0 = (tgt[lane]      > 0.f) ? lane      : -1;
        int v1 = (tgt[lane + 32] > 0.f) ? lane + 32 : -1;
        int v = max(v0, v1);
        #pragma unroll
        for (int off = 16; off > 0; off >>= 1)
            v = max(v, __shfl_xor_sync(0xffffffffu, v, off));
        if (lane == 0) s_last[wid] = v;
    }
    __syncthreads();
    const int last_r = s_last[0], last_c = s_last[1];
    const int size = (last_r >= 0 && last_c >= 0) ? (max(last_r, last_c) + 1)
                                                  : FALLBACK_SIZE;
    const float sz = (float)size;

    // ================= Phase C: masked sums from shared =================
    // Row pass: thread (i, cg) re-reads its row slice.
    const float rmask = (i < size) ? 1.f : 0.f;
    float rowacc = 0.f;
    float binsum = 0.f;
    {
        #pragma unroll
        for (int q = 0; q < 4; q++) {
            float4 sv  = *(const float4*)&s_s [i][cg * 16 + q * 4];
            float4 g2v = *(const float4*)&s_g2[i][cg * 16 + q * 4];
            const int j0 = cg * 16 + q * 4;
            float m0 = (j0 + 0 < size) ? 1.f : 0.f;
            float m1 = (j0 + 1 < size) ? 1.f : 0.f;
            float m2 = (j0 + 2 < size) ? 1.f : 0.f;
            float m3 = (j0 + 3 < size) ? 1.f : 0.f;
            rowacc += sv.x * m0 + sv.y * m1 + sv.z * m2 + sv.w * m3;
            binsum += g2v.x * m0 + g2v.y * m1 + g2v.z * m2 + g2v.w * m3;
        }
    }
    binsum *= rmask;
    // actual_rows[i]: sum across the 4 column-group lanes
    rowacc += __shfl_xor_sync(0xffffffffu, rowacc, 1);
    rowacc += __shfl_xor_sync(0xffffffffu, rowacc, 2);
    float rowerr = 0.f;
    if (cg == 0 && i < size) {
        const float d = rowacc - s_row_target[i];
        rowerr = d * d;
    }

    // Col pass: thread -> col j = t%64, row quarter rq = t/64 (16 rows).
    {
        const int j  = t & 63;
        const int rq = t >> 6;
        float csum = 0.f;
        #pragma unroll
        for (int rr = 0; rr < 16; rr++) {
            const int r = rq * 16 + rr;
            const float m = (r < size) ? 1.f : 0.f;
            csum += m * s_s[r][j];
        }
        s_cp[rq][j] = csum;
    }
    __syncthreads();

    float colerr = 0.f;
    if (t < NN && t < size) {
        const float csum = s_cp[0][t] + s_cp[1][t] + s_cp[2][t] + s_cp[3][t];
        const float d = csum - s_col_target[t];
        colerr = d * d;
    }

    // ================= Combine + block reduce ==========================
    float v = neural
            + (10.f / sz) * (rowerr + colerr)
            + (0.1f / (sz * sz)) * binsum;

    #pragma unroll
    for (int off = 16; off > 0; off >>= 1)
        v += __shfl_xor_sync(0xffffffffu, v, off);
    if (lane == 0) s_warp[wid] = v;
    __syncthreads();
    if (t == 0) {
        float p = 0.f;
        #pragma unroll
        for (int w = 0; w < 8; w++) p += s_warp[w];
        g_partials[b] = p;
        __threadfence();
        unsigned old = atomicInc(&g_count, BATCH - 1);   // wraps -> replay-safe
        s_is_last = (old == BATCH - 1);
    }
    __syncthreads();

    // ================= Last block: final reduction =====================
    if (s_is_last) {
        double acc = 0.0;
        #pragma unroll
        for (int q = 0; q < BATCH / 256; q++)
            acc += (double)g_partials[t + q * 256];
        #pragma unroll
        for (int off = 16; off > 0; off >>= 1)
            acc += __shfl_xor_sync(0xffffffffu, acc, off);
        if (lane == 0) s_dwarp[wid] = acc;
        __syncthreads();
        if (t < 8) {
            acc = s_dwarp[t];
            acc += __shfl_xor_sync(0xffu, acc, 4);
            acc += __shfl_xor_sync(0xffu, acc, 2);
            acc += __shfl_xor_sync(0xffu, acc, 1);
            if (t == 0) out[0] = (float)(acc * (1.0 / (double)BATCH));
        }
    }
}

extern "C" void kernel_launch(void* const* d_in, const int* in_sizes, int n_in,
                              void* d_out, int out_size) {
    const float* grid  = (const float*)d_in[0];
    const float* hints = (const float*)d_in[1];
    const float* wg    = (const float*)d_in[2];
    const float* wh    = (const float*)d_in[3];
    float* out = (float*)d_out;

    energy_kernel<<<BATCH, 256>>>(grid, hints, wg, wh, out);
}

// round 4
// speedup vs baseline: 1.6929x; 1.6929x over previous
#include <cuda_runtime.h>

#define BATCH 4096
#define NN 64
#define HH 16
#define FALLBACK_SIZE 12

__device__ float    g_partials[BATCH];
__device__ unsigned g_count = 0;

__device__ __forceinline__ float sigmoid3(float g) {
    float th;
    asm("tanh.approx.f32 %0, %1;" : "=f"(th) : "f"(1.5f * g));
    return fmaf(0.5f, th, 0.5f);
}

__global__ __launch_bounds__(256, 5) void energy_kernel(
    const float* __restrict__ grid,   // [B,1,64,64]
    const float* __restrict__ hints,  // [B,2,64,16]
    const float* __restrict__ wg,     // [1,64,64]
    const float* __restrict__ wh,     // [2,64,16]
    float* __restrict__ out)
{
    __shared__ float s_row_target[NN];
    __shared__ float s_col_target[NN];
    __shared__ float s_colpart[8 * NN];   // per-warp column partials
    __shared__ float s_warp[8];
    __shared__ int   s_last[2];
    __shared__ bool  s_is_last;
    __shared__ double s_dwarp[8];

    const int b = blockIdx.x;
    const int t = threadIdx.x;
    const int lane = t & 31;
    const int wid  = t >> 5;

    const float* gb = grid  + (size_t)b * (NN * NN);
    const float* hb = hints + (size_t)b * (2 * NN * HH);

    float neural = 0.f;

    // ---- Phase 1: hints -> targets (+ neural part), all 256 threads ----
    // thread t handles half a hint row: k = t>>7, r = (t>>1)&63, half = t&1
    {
        const int k    = t >> 7;
        const int r    = (t >> 1) & 63;
        const int half = t & 1;
        const float4* hp = (const float4*)(hb + k * (NN * HH) + r * HH + half * 8);
        const float4* wp = (const float4*)(wh + k * (NN * HH) + r * HH + half * 8);
        float tsum = 0.f;
        #pragma unroll
        for (int q = 0; q < 2; q++) {
            float4 h = hp[q];
            float4 w = wp[q];
            tsum   += h.x + h.y + h.z + h.w;
            neural += h.x * w.x + h.y * w.y + h.z * w.z + h.w * w.w;
        }
        tsum += __shfl_xor_sync(0xffffffffu, tsum, 1);  // combine the two halves
        if (half == 0) {
            if (k == 0) s_row_target[r] = tsum;
            else        s_col_target[r] = tsum;
        }
    }
    __syncthreads();

    // ---- Phase 2: puzzle size (warps 0,1 do a parallel arg-scan) ----
    if (wid < 2) {
        const float* tgt = (wid == 0) ? s_row_target : s_col_target;
        int v0 = (tgt[lane]      > 0.f) ? lane      : -1;
        int v1 = (tgt[lane + 32] > 0.f) ? lane + 32 : -1;
        int v = max(v0, v1);
        #pragma unroll
        for (int off = 16; off > 0; off >>= 1)
            v = max(v, __shfl_xor_sync(0xffffffffu, v, off));
        if (lane == 0) s_last[wid] = v;
    }
    __syncthreads();
    const int last_r = s_last[0], last_c = s_last[1];
    const int size = (last_r >= 0 && last_c >= 0) ? (max(last_r, last_c) + 1)
                                                  : FALLBACK_SIZE;
    const float sz = (float)size;

    // ---- Phase 3: grid pass — thread t -> row i = t/4, cols cg*16..+15 ----
    const int i  = t >> 2;
    const int cg = t & 3;
    const bool rin = (i < size);
    const float rmask = rin ? 1.f : 0.f;

    const float4* gp  = (const float4*)(gb + i * NN + cg * 16);
    const float4* wgp = (const float4*)(wg + i * NN + cg * 16);

    float csg[16];          // masked sigmoid values (for column sums)
    float rowacc = 0.f;
    float binsum = 0.f;

    #pragma unroll
    for (int q = 0; q < 4; q++) {
        float4 g4 = gp[q];
        float4 w4 = wgp[q];
        float gs[4] = {g4.x, g4.y, g4.z, g4.w};
        float ws[4] = {w4.x, w4.y, w4.z, w4.w};
        #pragma unroll
        for (int e = 0; e < 4; e++) {
            const int j = cg * 16 + q * 4 + e;
            const float g = gs[e];
            neural += g * ws[e];
            const float s = sigmoid3(g);
            const float jmask = (j < size) ? 1.f : 0.f;
            rowacc += s * jmask;
            binsum += g * g * jmask;
            csg[q * 4 + e] = s * rmask;
        }
    }
    binsum *= rmask;

    // actual_rows[i]: reduce across the 4 column-group lanes
    rowacc += __shfl_xor_sync(0xffffffffu, rowacc, 1);
    rowacc += __shfl_xor_sync(0xffffffffu, rowacc, 2);
    float rowerr = 0.f;
    if (cg == 0 && rin) {
        const float d = rowacc - s_row_target[i];
        rowerr = d * d;
    }

    // actual_cols: reduce csg over the 8 rows in this warp
    // (lane = ((i&7)<<2)|cg  ->  xor 4,8,16 toggles row bits)
    #pragma unroll
    for (int x = 0; x < 16; x++) {
        csg[x] += __shfl_xor_sync(0xffffffffu, csg[x], 4);
        csg[x] += __shfl_xor_sync(0xffffffffu, csg[x], 8);
        csg[x] += __shfl_xor_sync(0xffffffffu, csg[x], 16);
    }
    if (lane < 4) {
        #pragma unroll
        for (int x = 0; x < 16; x++)
            s_colpart[wid * NN + lane * 16 + x] = csg[x];
    }
    __syncthreads();

    float colerr = 0.f;
    if (t < NN && t < size) {
        float csum = 0.f;
        #pragma unroll
        for (int w = 0; w < 8; w++) csum += s_colpart[w * NN + t];
        const float d = csum - s_col_target[t];
        colerr = d * d;
    }

    // ---- Combine + block reduce ----
    float v = neural
            + (10.f / sz) * (rowerr + colerr)
            + (0.1f / (sz * sz)) * binsum;

    #pragma unroll
    for (int off = 16; off > 0; off >>= 1)
        v += __shfl_xor_sync(0xffffffffu, v, off);
    if (lane == 0) s_warp[wid] = v;
    __syncthreads();
    if (t == 0) {
        float p = 0.f;
        #pragma unroll
        for (int w = 0; w < 8; w++) p += s_warp[w];
        g_partials[b] = p;
        __threadfence();
        unsigned old = atomicInc(&g_count, BATCH - 1);   // wraps -> replay-safe
        s_is_last = (old == BATCH - 1);
    }
    __syncthreads();

    // ---- Last block: final reduction over all partials ----
    if (s_is_last) {
        double acc = 0.0;
        #pragma unroll
        for (int q = 0; q < BATCH / 256; q++)
            acc += (double)g_partials[t + q * 256];
        #pragma unroll
        for (int off = 16; off > 0; off >>= 1)
            acc += __shfl_xor_sync(0xffffffffu, acc, off);
        if (lane == 0) s_dwarp[wid] = acc;
        __syncthreads();
        if (t < 8) {
            acc = s_dwarp[t];
            acc += __shfl_xor_sync(0xffu, acc, 4);
            acc += __shfl_xor_sync(0xffu, acc, 2);
            acc += __shfl_xor_sync(0xffu, acc, 1);
            if (t == 0) out[0] = (float)(acc * (1.0 / (double)BATCH));
        }
    }
}

extern "C" void kernel_launch(void* const* d_in, const int* in_sizes, int n_in,
                              void* d_out, int out_size) {
    const float* grid  = (const float*)d_in[0];
    const float* hints = (const float*)d_in[1];
    const float* wg    = (const float*)d_in[2];
    const float* wh    = (const float*)d_in[3];
    float* out = (float*)d_out;

    energy_kernel<<<BATCH, 256>>>(grid, hints, wg, wh, out);
}